// round 7
// baseline (speedup 1.0000x reference)
#include <cuda_runtime.h>
#include <math.h>

#define TT 128
#define BB 32
#define EE 512
#define HH 512
#define UU 1024
#define VV 10000
#define G4 2048   // 4*H

// recurrence: 32 h-col tiles (16 cols) x 4 batch groups (8 b)
#define NBLK 128
#define PSTRIDE 68                 // padded row stride in partials (floats)
#define PSLICE  (8 * PSTRIDE)      // 544 floats per slice
#define PPAR    (8 * PSLICE)       // 4352 floats per parity
#define SMEM_LSTM (131072 + 32768 + 2 * PPAR * 4)   // Wt + hsd + Pp[2] = 194KB

// ---------------- scratch (static device globals; no allocation) ----------------
__device__ __align__(128) float g_X1 [TT*G4*BB];   // pregates [t][g4][b]
__device__ __align__(128) float g_H1 [TT*BB*HH];
__device__ __align__(128) float g_S  [TT*BB*UU];
__device__ __align__(128) float g_CTX[TT*BB*HH];
__device__ __align__(128) float g_X2 [TT*G4*BB];   // pregates [t][g4][b]
__device__ __align__(128) float g_HS [TT*BB*HH];
__device__ __align__(128) float g_HT [2][4*512*8]; // parity h [bg][k][b8]
__device__ unsigned g_flag[NBLK];                  // [bg*32 + hc], monotonic

// ---------------- helpers ----------------
typedef unsigned long long ull;
__device__ __forceinline__ ull pack2(float x) {
    ull r;
    asm("mov.b64 %0, {%1, %1};" : "=l"(r) : "r"(__float_as_uint(x)));
    return r;
}
__device__ __forceinline__ void fma2(ull& d, ull a, ull b) {
    asm("fma.rn.f32x2 %0, %1, %2, %0;" : "+l"(d) : "l"(a), "l"(b));
}
__device__ __forceinline__ unsigned ld_acq(const unsigned* p) {
    unsigned v;
    asm volatile("ld.acquire.gpu.global.u32 %0, [%1];" : "=r"(v) : "l"(p));
    return v;
}
__device__ __forceinline__ void st_rel(unsigned* p, unsigned v) {
    asm volatile("st.release.gpu.global.u32 [%0], %1;" :: "l"(p), "r"(v) : "memory");
}
__device__ __forceinline__ float sigmoidf_(float x) { return 1.f / (1.f + expf(-x)); }

// ---------------- prep: reset flags, h0 -> g_HT[1] in [bg][k][b8] layout --------
__global__ void prep(const float* __restrict__ h0row)
{
    int tid = threadIdx.x;
    if (tid < NBLK) g_flag[tid] = 0;
    for (int idx = tid; idx < BB * HH; idx += 256) {
        int b = idx >> 9, h = idx & 511;
        g_HT[1][(b >> 3) * 4096 + h * 8 + (b & 7)] = h0row[idx];
    }
}

// ---------------- persistent LSTM recurrence -----------------------------------
// Block (hc, bg): h-cols [16hc,16hc+16), batches [8bg,8bg+8), full K=512.
// Warp w = k-slice [64w,64w+64): depends ONLY on blocks hc'=4w..4w+3 of its own
// batch group. Per step per warp: poll 4 flags -> stage private 2KB h slice ->
// compute (f32x2, W pairs x dup-h) -> store partials (parity buffer). One block
// barrier; reducers (tid<128) sum slices + pointwise, publish h, release flag.
__global__ __launch_bounds__(256)
void lstm_seq(const float* __restrict__ XT,     // [T][G4][B] pregates
              const float* __restrict__ Whh,    // [G4][H]
              const float* __restrict__ c0row,  // [B][H]
              float* __restrict__ Hout)         // [T][B][H]
{
    extern __shared__ char smraw[];
    float* Wt  = (float*)smraw;                   // [512][64]  W (rows r=g*16+j)
    ull*   hsd = (ull*)(smraw + 131072);          // [512][8]   dup h pairs
    float* Pp  = (float*)(smraw + 131072 + 32768);// [2][8][8b][PSTRIDE]

    const int bid = blockIdx.x;
    const int tid = threadIdx.x;
    const int hc  = bid & 31;
    const int bg  = bid >> 5;

    // ---- stage W once: Wt[k][r], r = g*16+j -> gate row g*512+16hc+j ----
    for (int idx = tid; idx < 64 * 128; idx += 256) {
        int r  = idx & 63;
        int k4 = idx >> 6;
        int g = r >> 4, j = r & 15;
        int gr = g * 512 + 16 * hc + j;
        float4 w = *(const float4*)(Whh + (size_t)gr * HH + k4 * 4);
        Wt[(k4 * 4 + 0) * 64 + r] = w.x;
        Wt[(k4 * 4 + 1) * 64 + r] = w.y;
        Wt[(k4 * 4 + 2) * 64 + r] = w.z;
        Wt[(k4 * 4 + 3) * 64 + r] = w.w;
    }

    const int warp = tid >> 5;
    const int lane = tid & 31;
    const int rs   = lane & 15;        // rowset: rows 4rs..4rs+3
    const int bset = lane >> 4;        // batches 4bset..4bset+3
    const int kbeg = warp * 64;

    // reducer role (tid < 128): cell (jc, bb)
    const int jc = tid >> 3;           // 0..15 h-col within tile
    const int bb = tid & 7;            // 0..7 batch within group
    float cv = 0.f;
    if (tid < 128) cv = c0row[(8 * bg + bb) * HH + 16 * hc + jc];

    unsigned* myflag = &g_flag[bid];
    const unsigned* depflags = &g_flag[bg * 32 + warp * 4];  // 4 deps per warp

    __syncthreads();   // W staged

    for (int t = 0; t < TT; t++) {
        const int p = t & 1;

        // ---- per-warp wait: the 4 producer blocks of this k-slice ----
        if (t > 0) {
            bool done = (lane >= 4);
            const unsigned tgt = (unsigned)t;
            while (!__all_sync(0xffffffffu, done)) {
                if (!done) done = (ld_acq(depflags + lane) >= tgt);
            }
        }
        __syncwarp();

        // ---- stage own 64-k h slice -> hsd (duplicated pairs) ----
        {
            const float4* src =
                (const float4*)&g_HT[(t + 1) & 1][bg * 4096 + kbeg * 8];
            #pragma unroll
            for (int r = 0; r < 4; r++) {
                int i = lane + r * 32;            // 0..127 float4
                float4 v = __ldcg(src + i);
                ull* d = &hsd[(kbeg + (i >> 1)) * 8 + (i & 1) * 4];
                d[0] = pack2(v.x); d[1] = pack2(v.y);
                d[2] = pack2(v.z); d[3] = pack2(v.w);
            }
        }
        __syncwarp();

        // ---- compute: 4 rows (2 pairs) x 4 batches x 64 k ----
        ull acc[2][4];
        #pragma unroll
        for (int i = 0; i < 2; i++)
            #pragma unroll
            for (int q = 0; q < 4; q++) acc[i][q] = 0ull;

        #pragma unroll 4
        for (int k = kbeg; k < kbeg + 64; k++) {
            ulonglong2 w2 = *(const ulonglong2*)&Wt[k * 64 + rs * 4];
            ulonglong2 hA = *(const ulonglong2*)&hsd[k * 8 + bset * 4];
            ulonglong2 hB = *(const ulonglong2*)&hsd[k * 8 + bset * 4 + 2];
            fma2(acc[0][0], w2.x, hA.x); fma2(acc[0][1], w2.x, hA.y);
            fma2(acc[0][2], w2.x, hB.x); fma2(acc[0][3], w2.x, hB.y);
            fma2(acc[1][0], w2.y, hA.x); fma2(acc[1][1], w2.y, hA.y);
            fma2(acc[1][2], w2.y, hB.x); fma2(acc[1][3], w2.y, hB.y);
        }

        // ---- store partials: Pp[p][warp][b][row] (padded) ----
        {
            float* pb = Pp + p * PPAR + warp * PSLICE;
            #pragma unroll
            for (int jp = 0; jp < 2; jp++)
                #pragma unroll
                for (int q = 0; q < 4; q++)
                    *(ull*)&pb[(bset * 4 + q) * PSTRIDE + 4 * rs + 2 * jp] =
                        acc[jp][q];
        }

        // ---- XT prefetch for reducers (off critical path) ----
        float xg0 = 0.f, xg1 = 0.f, xg2 = 0.f, xg3 = 0.f;
        if (tid < 128) {
            const float* xb = XT + ((size_t)t * G4 + 16 * hc + jc) * BB
                              + 8 * bg + bb;
            xg0 = __ldcg(xb);
            xg1 = __ldcg(xb + (size_t)512  * BB);
            xg2 = __ldcg(xb + (size_t)1024 * BB);
            xg3 = __ldcg(xb + (size_t)1536 * BB);
        }

        __syncthreads();   // all partials of step t in Pp[p]

        // ---- reduce + pointwise + publish (tid < 128) ----
        if (tid < 128) {
            const float* pbase = Pp + p * PPAR + bb * PSTRIDE;
            float g0 = xg0, g1 = xg1, g2 = xg2, g3 = xg3;
            #pragma unroll
            for (int s = 0; s < 8; s++) {
                const float* ps = pbase + s * PSLICE;
                g0 += ps[jc];
                g1 += ps[16 + jc];
                g2 += ps[32 + jc];
                g3 += ps[48 + jc];
            }
            float gi = sigmoidf_(g0);
            float gf = sigmoidf_(g1);
            float gg = tanhf(g2);
            float go = sigmoidf_(g3);
            cv = gf * cv + gi * gg;
            float hv = go * tanhf(cv);

            // publish h for the chain, then release, then archive Hout
            g_HT[t & 1][bg * 4096 + (16 * hc + jc) * 8 + bb] = hv;
            asm volatile("bar.sync 1, 128;" ::: "memory");
            if (tid == 0) st_rel(myflag, (unsigned)(t + 1));
            Hout[(size_t)t * BB * HH + (8 * bg + bb) * HH + 16 * hc + jc] = hv;
        }
    }
}

// ---------------- SGEMM  C = A(MxK) * B(NxK)^T + bias1 + bias2 ----------------
// transC=1: store C[(m>>5)][n][m&31] ([t][g4][b]) for the X pregate GEMMs.
__global__ __launch_bounds__(256)
void sgemm_tn(const float* __restrict__ A, const float* __restrict__ B,
              float* __restrict__ C,
              const float* __restrict__ bias1, const float* __restrict__ bias2,
              int M, int N, int K, int lda, int ldb, int ldc,
              long long aBS, long long bBS, long long cBS, int transC)
{
    __shared__ float As[16][64];
    __shared__ float Bs[16][64];

    const int tid = threadIdx.x;
    const int tx = tid & 15;
    const int ty = tid >> 4;
    const int m0 = blockIdx.y * 64;
    const int n0 = blockIdx.x * 64;

    const float* Ab = A + (long long)blockIdx.z * aBS;
    const float* Bb = B + (long long)blockIdx.z * bBS;
    float*       Cb = C + (long long)blockIdx.z * cBS;

    const int lr = tid >> 2;
    const int lk = (tid & 3) << 2;

    float acc[4][4];
    #pragma unroll
    for (int i = 0; i < 4; i++)
        #pragma unroll
        for (int q = 0; q < 4; q++) acc[i][q] = 0.f;

    for (int kt = 0; kt < K; kt += 16) {
        {
            int m = m0 + lr;
            float4 v = make_float4(0.f, 0.f, 0.f, 0.f);
            if (m < M) v = *(const float4*)(Ab + (size_t)m * lda + kt + lk);
            As[lk + 0][lr] = v.x; As[lk + 1][lr] = v.y;
            As[lk + 2][lr] = v.z; As[lk + 3][lr] = v.w;
        }
        {
            int n = n0 + lr;
            float4 v = make_float4(0.f, 0.f, 0.f, 0.f);
            if (n < N) v = *(const float4*)(Bb + (size_t)n * ldb + kt + lk);
            Bs[lk + 0][lr] = v.x; Bs[lk + 1][lr] = v.y;
            Bs[lk + 2][lr] = v.z; Bs[lk + 3][lr] = v.w;
        }
        __syncthreads();
        #pragma unroll
        for (int k = 0; k < 16; k++) {
            float a[4], b[4];
            *(float4*)a = *(const float4*)&As[k][ty << 2];
            *(float4*)b = *(const float4*)&Bs[k][tx << 2];
            #pragma unroll
            for (int i = 0; i < 4; i++)
                #pragma unroll
                for (int q = 0; q < 4; q++)
                    acc[i][q] += a[i] * b[q];
        }
        __syncthreads();
    }

    #pragma unroll
    for (int i = 0; i < 4; i++) {
        int m = m0 + (ty << 2) + i;
        if (m >= M) continue;
        #pragma unroll
        for (int q = 0; q < 4; q++) {
            int n = n0 + (tx << 2) + q;
            if (n < N) {
                float v = acc[i][q];
                if (bias1) v += bias1[n];
                if (bias2) v += bias2[n];
                if (transC)
                    Cb[((size_t)(m >> 5) * G4 + n) * BB + (m & 31)] = v;
                else
                    Cb[(size_t)m * ldc + n] = v;
            }
        }
    }
}

// ---------------- SGEMM  C = A(MxK) * B(KxN) ----------------
__global__ __launch_bounds__(256)
void sgemm_nn(const float* __restrict__ A, const float* __restrict__ B,
              float* __restrict__ C,
              int M, int N, int K, int lda, int ldb, int ldc,
              long long aBS, long long bBS, long long cBS)
{
    __shared__ float As[16][64];
    __shared__ float Bs[16][64];

    const int tid = threadIdx.x;
    const int tx = tid & 15;
    const int ty = tid >> 4;
    const int m0 = blockIdx.y * 64;
    const int n0 = blockIdx.x * 64;

    const float* Ab = A + (long long)blockIdx.z * aBS;
    const float* Bb = B + (long long)blockIdx.z * bBS;
    float*       Cb = C + (long long)blockIdx.z * cBS;

    const int lr = tid >> 2;
    const int lk = (tid & 3) << 2;
    const int bkr = tid >> 4;
    const int bnc = (tid & 15) << 2;

    float acc[4][4];
    #pragma unroll
    for (int i = 0; i < 4; i++)
        #pragma unroll
        for (int q = 0; q < 4; q++) acc[i][q] = 0.f;

    for (int kt = 0; kt < K; kt += 16) {
        {
            int m = m0 + lr;
            float4 v = make_float4(0.f, 0.f, 0.f, 0.f);
            if (m < M) v = *(const float4*)(Ab + (size_t)m * lda + kt + lk);
            As[lk + 0][lr] = v.x; As[lk + 1][lr] = v.y;
            As[lk + 2][lr] = v.z; As[lk + 3][lr] = v.w;
        }
        {
            int n = n0 + bnc;
            float4 v = make_float4(0.f, 0.f, 0.f, 0.f);
            if (n < N) v = *(const float4*)(Bb + (size_t)(kt + bkr) * ldb + n);
            *(float4*)&Bs[bkr][bnc] = v;
        }
        __syncthreads();
        #pragma unroll
        for (int k = 0; k < 16; k++) {
            float a[4], b[4];
            *(float4*)a = *(const float4*)&As[k][ty << 2];
            *(float4*)b = *(const float4*)&Bs[k][tx << 2];
            #pragma unroll
            for (int i = 0; i < 4; i++)
                #pragma unroll
                for (int q = 0; q < 4; q++)
                    acc[i][q] += a[i] * b[q];
        }
        __syncthreads();
    }

    #pragma unroll
    for (int i = 0; i < 4; i++) {
        int m = m0 + (ty << 2) + i;
        if (m >= M) continue;
        #pragma unroll
        for (int q = 0; q < 4; q++) {
            int n = n0 + (tx << 2) + q;
            if (n < N) Cb[(size_t)m * ldc + n] = acc[i][q];
        }
    }
}

// ---------------- row softmax (in place) ----------------
__global__ __launch_bounds__(256)
void softmax_rows(float* __restrict__ data, int L)
{
    float* p = data + (size_t)blockIdx.x * L;
    __shared__ float red[256];
    const int tid = threadIdx.x;

    float m = -3.4e38f;
    for (int i = tid; i < L; i += 256) m = fmaxf(m, p[i]);
    red[tid] = m; __syncthreads();
    #pragma unroll
    for (int s = 128; s > 0; s >>= 1) {
        if (tid < s) red[tid] = fmaxf(red[tid], red[tid + s]);
        __syncthreads();
    }
    m = red[0]; __syncthreads();

    float sum = 0.f;
    for (int i = tid; i < L; i += 256) {
        float e = expf(p[i] - m);
        p[i] = e;
        sum += e;
    }
    red[tid] = sum; __syncthreads();
    #pragma unroll
    for (int s = 128; s > 0; s >>= 1) {
        if (tid < s) red[tid] += red[tid + s];
        __syncthreads();
    }
    const float inv = 1.f / red[0];
    for (int i = tid; i < L; i += 256) p[i] *= inv;
}

// ---------------- launch ----------------
extern "C" void kernel_launch(void* const* d_in, const int* in_sizes, int n_in,
                              void* d_out, int out_size)
{
    const float* inputs = (const float*)d_in[0];
    const float* h0     = (const float*)d_in[1];
    const float* c0     = (const float*)d_in[2];
    const float* Lst    = (const float*)d_in[3];
    const float* W_ih1  = (const float*)d_in[4];
    const float* W_hh1  = (const float*)d_in[5];
    const float* b_ih1  = (const float*)d_in[6];
    const float* b_hh1  = (const float*)d_in[7];
    const float* W_ih2  = (const float*)d_in[8];
    const float* W_hh2  = (const float*)d_in[9];
    const float* b_ih2  = (const float*)d_in[10];
    const float* b_hh2  = (const float*)d_in[11];
    const float* W_out  = (const float*)d_in[12];
    const float* b_out  = (const float*)d_in[13];
    float* out = (float*)d_out;

    void* p;
    cudaGetSymbolAddress(&p, g_X1);  float* X1  = (float*)p;
    cudaGetSymbolAddress(&p, g_H1);  float* H1  = (float*)p;
    cudaGetSymbolAddress(&p, g_S);   float* S   = (float*)p;
    cudaGetSymbolAddress(&p, g_CTX); float* CTX = (float*)p;
    cudaGetSymbolAddress(&p, g_X2);  float* X2  = (float*)p;
    cudaGetSymbolAddress(&p, g_HS);  float* HS  = (float*)p;

    cudaFuncSetAttribute(lstm_seq, cudaFuncAttributeMaxDynamicSharedMemorySize,
                         SMEM_LSTM);

    // X1 = inputs @ W_ih1^T + biases, stored [t][g4][b]
    {
        dim3 g(G4 / 64, (TT * BB) / 64, 1);
        sgemm_tn<<<g, 256>>>(inputs, W_ih1, X1, b_ih1, b_hh1,
                             TT * BB, G4, EE, EE, EE, G4, 0, 0, 0, 1);
    }

    // layer-1 recurrence
    prep<<<1, 256>>>(h0);
    lstm_seq<<<NBLK, 256, SMEM_LSTM>>>(X1, W_hh1, c0, H1);

    // attention: S[t,b,u] = sum_h H1[t,b,h] * L[u,b,h]
    {
        dim3 g(UU / 64, TT / 64, BB);
        sgemm_tn<<<g, 256>>>(H1, Lst, S, nullptr, nullptr,
                             TT, UU, HH, BB * HH, BB * HH, BB * UU,
                             HH, HH, UU, 0);
    }
    softmax_rows<<<TT * BB, 256>>>(S, UU);
    // CTX[t,b,h] = sum_u S[t,b,u] * L[u,b,h]
    {
        dim3 g(HH / 64, TT / 64, BB);
        sgemm_nn<<<g, 256>>>(S, Lst, CTX,
                             TT, HH, UU, BB * UU, BB * HH, BB * HH,
                             UU, HH, HH);
    }

    // X2 = CTX @ W_ih2^T + biases, stored [t][g4][b]
    {
        dim3 g(G4 / 64, (TT * BB) / 64, 1);
        sgemm_tn<<<g, 256>>>(CTX, W_ih2, X2, b_ih2, b_hh2,
                             TT * BB, G4, HH, HH, HH, G4, 0, 0, 0, 1);
    }

    // layer-2 recurrence
    prep<<<1, 256>>>(h0 + BB * HH);
    lstm_seq<<<NBLK, 256, SMEM_LSTM>>>(X2, W_hh2, c0 + BB * HH, HS);

    // logits = HS @ W_out^T + b_out -> softmax over V
    {
        dim3 g((VV + 63) / 64, (TT * BB) / 64, 1);
        sgemm_tn<<<g, 256>>>(HS, W_out, out, b_out, nullptr,
                             TT * BB, VV, HH, HH, HH, VV, 0, 0, 0, 0);
    }
    softmax_rows<<<TT * BB, 256>>>(out, VV);
}